// round 12
// baseline (speedup 1.0000x reference)
#include <cuda_runtime.h>
#include <cuda_bf16.h>
#include <cstdint>

#define BSZ  512
#define TLEN 512
#define IDIM 128
#define HDIM 50
#define ODIM 10
#define GDIM 200              // 4*H
#define BT   (BSZ * TLEN)     // 262144 rows

typedef unsigned long long u64;
typedef unsigned int u32;

// ---- scratch (device globals; no allocation allowed) ----
__device__ u32   g_Bimg[102400 / 4];   // W_ih bf16 hi/lo, mma-fragment-ordered
__device__ u32   g_Wh[12800];          // W_hh bf16 hi/lo frag image (25 tiles x 4 kc)
__device__ float g_bias[GDIM];         // b_ih + b_hh
__device__ float g_xp[BT * GDIM];      // x_proj: [row][g]

// ---- helpers ----
__device__ __forceinline__ float fast_sigmoid(float x) {
    return 1.f / (1.f + __expf(-x));
}
__device__ __forceinline__ void cp16(void* smem, const void* gmem) {
    unsigned sa = (unsigned)__cvta_generic_to_shared(smem);
    asm volatile("cp.async.cg.shared.global [%0], [%1], 16;\n" :: "r"(sa), "l"(gmem));
}
__device__ __forceinline__ void split_bf16(float v, unsigned short& h, unsigned short& l) {
    __nv_bfloat16 hb = __float2bfloat16_rn(v);
    float lf = v - __bfloat162float(hb);
    __nv_bfloat16 lb = __float2bfloat16_rn(lf);
    h = __bfloat16_as_ushort(hb);
    l = __bfloat16_as_ushort(lb);
}
__device__ __forceinline__ void split2(float2 v, u32& hp, u32& lp) {
    unsigned short h0, l0, h1, l1;
    split_bf16(v.x, h0, l0);
    split_bf16(v.y, h1, l1);
    hp = (u32)h0 | ((u32)h1 << 16);
    lp = (u32)l0 | ((u32)l1 << 16);
}
__device__ __forceinline__ void mma16816(float* c, const u32* a, u32 b0, u32 b1) {
    asm volatile(
        "mma.sync.aligned.m16n8k16.row.col.f32.bf16.bf16.f32 "
        "{%0,%1,%2,%3}, {%4,%5,%6,%7}, {%8,%9}, {%0,%1,%2,%3};"
        : "+f"(c[0]), "+f"(c[1]), "+f"(c[2]), "+f"(c[3])
        : "r"(a[0]), "r"(a[1]), "r"(a[2]), "r"(a[3]), "r"(b0), "r"(b1));
}

// ============================================================
// Kernel 0: W_ih fragment image + bias.
// ============================================================
__global__ void prep(const float* __restrict__ W_ih,
                     const float* __restrict__ b_ih,
                     const float* __restrict__ b_hh) {
    int t = threadIdx.x + blockIdx.x * 256;
    for (int idx = t; idx < GDIM * (IDIM / 2); idx += 256 * 32) {
        int g  = idx >> 6;
        int k2 = (idx & 63) * 2;
        u32 hp, lp;
        split2(*(const float2*)&W_ih[g * IDIM + k2], hp, lp);
        int nt = g >> 3, nloc = g & 7;
        int kc = k2 >> 4, kloc = k2 & 15;
        int lane = nloc * 4 + ((kloc & 7) >> 1);
        int reg  = kloc >> 3;
        int base = ((kc * 25 + nt) * 32 + lane) * 4;
        g_Bimg[base + reg]     = hp;
        g_Bimg[base + 2 + reg] = lp;
    }
    if (blockIdx.x == 0 && t < GDIM) g_bias[t] = b_ih[t] + b_hh[t];
}

// ============================================================
// Kernel 0b: W_hh fragment image (K padded 50 -> 64 with zeros).
// 200 gates x 32 k-pairs.
// ============================================================
__global__ void prep2(const float* __restrict__ W_hh) {
    int t = threadIdx.x + blockIdx.x * 256;
#pragma unroll
    for (int u = 0; u < 4; u++) {
        int idx = t + u * 2048;
        if (idx < GDIM * 32) {
            int g  = idx >> 5;
            int k2 = (idx & 31) * 2;
            float w0 = (k2     < HDIM) ? W_hh[g * HDIM + k2]     : 0.f;
            float w1 = (k2 + 1 < HDIM) ? W_hh[g * HDIM + k2 + 1] : 0.f;
            u32 hp, lp;
            split2(make_float2(w0, w1), hp, lp);
            int nt = g >> 3, nloc = g & 7;
            int kc = k2 >> 4, kloc = k2 & 15;
            int lane = nloc * 4 + ((kloc & 7) >> 1);
            int reg  = kloc >> 3;
            int base = ((kc * 25 + nt) * 32 + lane) * 4;
            g_Wh[base + reg]     = hp;
            g_Wh[base + 2 + reg] = lp;
        }
    }
}

// ============================================================
// Kernel 1: HMMA GEMM (unchanged R11, measured ~125us).
// ============================================================
#define SM_B    0                // 102400 B
#define SM_BIAS 102400           // 800 B
#define MMA_SMEM 103296

__global__ __launch_bounds__(512, 1) void gemm_mma(const float* __restrict__ x) {
    extern __shared__ char sm[];
    u32*   bImg = (u32*)(sm + SM_B);
    float* bias = (float*)(sm + SM_BIAS);

    const int tid = threadIdx.x;
    const int w   = tid >> 5;
    const int l   = tid & 31;
    const int row0 = blockIdx.x * 128;

#pragma unroll
    for (int u = 0; u < 12; u++) {
        int idx = tid + u * 512;
        cp16(bImg + idx * 4, g_Bimg + idx * 4);
    }
    if (tid < 256) {
        int idx = 6144 + tid;
        cp16(bImg + idx * 4, g_Bimg + idx * 4);
    }
    asm volatile("cp.async.commit_group;\n" ::: "memory");
    if (tid < GDIM) bias[tid] = g_bias[tid];

    const int mt  = w & 7;
    const int nh  = w >> 3;
    const int n0  = nh * 13;
    const int cnt = nh ? 12 : 13;

    const int rA = row0 + mt * 16 + (l >> 2);
    const float* xr0 = x + (size_t)rA * IDIM + (l & 3) * 2;
    const float* xr1 = xr0 + 8 * IDIM;

    float acc[13][4];
#pragma unroll
    for (int n = 0; n < 13; n++)
#pragma unroll
        for (int j = 0; j < 4; j++) acc[n][j] = 0.f;

    float2 v0 = *(const float2*)(xr0);
    float2 v1 = *(const float2*)(xr1);
    float2 v2 = *(const float2*)(xr0 + 8);
    float2 v3 = *(const float2*)(xr1 + 8);

    asm volatile("cp.async.wait_group 0;\n" ::: "memory");
    __syncthreads();

#pragma unroll
    for (int kc = 0; kc < 8; kc++) {
        u32 ahr[4], alr[4];
        split2(v0, ahr[0], alr[0]);
        split2(v1, ahr[1], alr[1]);
        split2(v2, ahr[2], alr[2]);
        split2(v3, ahr[3], alr[3]);
        if (kc + 1 < 8) {
            int ko = (kc + 1) * 16;
            v0 = *(const float2*)(xr0 + ko);
            v1 = *(const float2*)(xr1 + ko);
            v2 = *(const float2*)(xr0 + ko + 8);
            v3 = *(const float2*)(xr1 + ko + 8);
        }
#pragma unroll
        for (int n = 0; n < 13; n++) {
            if (n < cnt) {
                uint4 b = *(const uint4*)&bImg[((kc * 25 + n0 + n) * 32 + l) * 4];
                mma16816(acc[n], ahr, b.x, b.y);
                mma16816(acc[n], ahr, b.z, b.w);
                mma16816(acc[n], alr, b.x, b.y);
            }
        }
    }
    {
        int r0 = row0 + mt * 16 + (l >> 2);
        int r1 = r0 + 8;
#pragma unroll
        for (int n = 0; n < 13; n++) {
            if (n < cnt) {
                int c = (n0 + n) * 8 + (l & 3) * 2;
                float2 bv = *(const float2*)&bias[c];
                float2 o0 = make_float2(acc[n][0] + bv.x, acc[n][1] + bv.y);
                float2 o1 = make_float2(acc[n][2] + bv.x, acc[n][3] + bv.y);
                *(float2*)&g_xp[(size_t)r0 * GDIM + c] = o0;
                *(float2*)&g_xp[(size_t)r1 * GDIM + c] = o1;
            }
        }
    }
}

// ============================================================
// Kernel 2: LSTM recurrence via HMMA. 128 blocks x 4 batches,
// 256 threads. Per step: gates = xp + h @ W_hh^T, 300 warp-MMAs
// (25 n-tiles x 4 kc x 3 hi/lo passes), activations at D-frag
// positions, c/h update by 100 threads, h re-split to A-frags.
// ============================================================
#define LB   4
#define LCH  4
// SMEM byte offsets
#define L_WF   0            // 51200: W_hh frag image
#define L_HFH  51200        // 2048:  h frags hi (4 kc x 32 x 4 u32)
#define L_HFL  53248        // 2048:  h frags lo
#define L_XB   55296        // 2 x 12800: xp chunks [buf][step][b][200]
#define L_GS   80896        // 3200:  activated gates [4][200]
#define L_HS   84096        // 800:   h fp32 [4][50]
#define L_SMEM 84992

__global__ __launch_bounds__(256, 1) void lstm_mma(
    const float* __restrict__ W_fc, const float* __restrict__ b_fc,
    float* __restrict__ out)
{
    extern __shared__ char sm[];
    u32*   wf  = (u32*)(sm + L_WF);
    u32*   hfh = (u32*)(sm + L_HFH);
    u32*   hfl = (u32*)(sm + L_HFL);
    float* xb  = (float*)(sm + L_XB);
    float* gs  = (float*)(sm + L_GS);
    float* hs  = (float*)(sm + L_HS);

    const int tid = threadIdx.x;
    const int w   = tid >> 5;
    const int l   = tid & 31;
    const int b0  = blockIdx.x * LB;

    // load W_hh frag image: 3200 x 16B
#pragma unroll
    for (int u = 0; u < 13; u++) {
        int idx = tid + u * 256;
        if (idx < 3200) cp16(wf + idx * 4, g_Wh + idx * 4);
    }
    asm volatile("cp.async.commit_group;\n" ::: "memory");

    // zero h fragments (512 u32 each)
#pragma unroll
    for (int u = 0; u < 2; u++) {
        hfh[tid + u * 256] = 0;
        hfl[tid + u * 256] = 0;
    }

    auto issue_chunk = [&](int t0, int buf) {
#pragma unroll
        for (int u = 0; u < 4; u++) {
            int idx = tid + u * 256;
            if (idx < 800) {                 // 4 steps x 4 b x 50 chunks
                int s  = idx / 200;
                int rm = idx % 200;
                int b  = rm / 50;
                int cq = rm % 50;
                const float* src = g_xp +
                    ((size_t)(b0 + b) * TLEN + (t0 + s)) * GDIM + cq * 4;
                cp16(xb + buf * 3200 + (s * LB + b) * 200 + cq * 4, src);
            }
        }
        asm volatile("cp.async.commit_group;\n" ::: "memory");
    };
    issue_chunk(0, 0);
    issue_chunk(LCH, 1);

    // warp n-tile assignment: {w, w+8, w+16}, warp 0 also tile 24
    int tiles[4];
    tiles[0] = w; tiles[1] = w + 8; tiles[2] = w + 16;
    tiles[3] = (w == 0) ? 24 : -1;

    float c0 = 0.f, c1 = 0.f;       // c-state for update threads (tid<100)
    int cur = 0;
    const int r  = l >> 2;
    const int cl = (l & 3) * 2;

    for (int t = 0; t < TLEN; t++) {
        int ts = t & (LCH - 1);
        if (ts == 0) {
            if (t + LCH < TLEN)
                asm volatile("cp.async.wait_group 1;\n" ::: "memory");
            else
                asm volatile("cp.async.wait_group 0;\n" ::: "memory");
            __syncthreads();
        }

        // ---- MMA phase ----
        const float* xs = xb + cur * 3200 + ts * 800;
        float acc[4][4];
#pragma unroll
        for (int ti = 0; ti < 4; ti++) {
            int nt = tiles[ti];
#pragma unroll
            for (int j = 0; j < 4; j++) acc[ti][j] = 0.f;
            if (nt >= 0 && l < 16) {        // rows 0..3 = real batches
                float2 v = *(const float2*)&xs[r * 200 + nt * 8 + cl];
                acc[ti][0] = v.x;
                acc[ti][1] = v.y;
            }
        }
#pragma unroll
        for (int kc = 0; kc < 4; kc++) {
            uint4 ah4 = *(const uint4*)&hfh[(kc * 32 + l) * 4];
            uint4 al4 = *(const uint4*)&hfl[(kc * 32 + l) * 4];
            u32 ahr[4] = {ah4.x, ah4.y, ah4.z, ah4.w};
            u32 alr[4] = {al4.x, al4.y, al4.z, al4.w};
#pragma unroll
            for (int ti = 0; ti < 4; ti++) {
                int nt = tiles[ti];
                if (nt >= 0) {
                    uint4 b4 = *(const uint4*)&wf[((kc * 25 + nt) * 32 + l) * 4];
                    mma16816(acc[ti], ahr, b4.x, b4.y);   // hi*hi
                    mma16816(acc[ti], ahr, b4.z, b4.w);   // hi*lo
                    mma16816(acc[ti], alr, b4.x, b4.y);   // lo*hi
                }
            }
        }
        // ---- activations at D-frag positions (rows 0..3 only) ----
        if (l < 16) {
#pragma unroll
            for (int ti = 0; ti < 4; ti++) {
                int nt = tiles[ti];
                if (nt >= 0) {
                    int c = nt * 8 + cl;
                    bool isg = (c >= 100 && c < 150);   // tanh gate (c,c+1 same type)
                    float v0 = acc[ti][0], v1 = acc[ti][1];
                    float z0 = isg ? v0 + v0 : v0;
                    float z1 = isg ? v1 + v1 : v1;
                    float s0 = fast_sigmoid(z0);
                    float s1 = fast_sigmoid(z1);
                    float2 res = make_float2(isg ? 2.f * s0 - 1.f : s0,
                                             isg ? 2.f * s1 - 1.f : s1);
                    *(float2*)&gs[r * 200 + c] = res;
                }
            }
        }
        __syncthreads();                     // B1: gates visible

        // ---- c/h update: 100 threads, one (batch, unit-pair) each ----
        if (tid < 100) {
            int b = tid / 25, p = tid % 25, u0 = 2 * p;
            float2 iv = *(const float2*)&gs[b * 200 + u0];
            float2 fv = *(const float2*)&gs[b * 200 + 50 + u0];
            float2 gv = *(const float2*)&gs[b * 200 + 100 + u0];
            float2 ov = *(const float2*)&gs[b * 200 + 150 + u0];
            c0 = fmaf(fv.x, c0, iv.x * gv.x);
            c1 = fmaf(fv.y, c1, iv.y * gv.y);
            float h0 = ov.x * (2.f * fast_sigmoid(c0 + c0) - 1.f);
            float h1 = ov.y * (2.f * fast_sigmoid(c1 + c1) - 1.f);
            *(float2*)&hs[b * 50 + u0] = make_float2(h0, h1);
            u32 hp, lp;
            split2(make_float2(h0, h1), hp, lp);
            int kc = u0 >> 4, kloc = u0 & 15;
            int lane2 = (b & 7) * 4 + ((kloc & 7) >> 1);
            int reg   = (kloc >> 3) * 2;            // rows b<8 -> +0
            int fidx  = (kc * 32 + lane2) * 4 + reg;
            hfh[fidx] = hp;
            hfl[fidx] = lp;
        }
        if (ts == LCH - 1 && t + LCH + 1 < TLEN) issue_chunk(t + LCH + 1, cur);
        __syncthreads();                     // B2: h frags visible
        if (ts == LCH - 1) cur ^= 1;
    }

    // FC head
    if (tid < LB * ODIM) {
        int b = tid / ODIM, o = tid % ODIM;
        float a = b_fc[o];
#pragma unroll
        for (int u = 0; u < HDIM; u++)
            a = fmaf(hs[b * 50 + u], W_fc[o * HDIM + u], a);
        out[(b0 + b) * ODIM + o] = a;
    }
}

// ============================================================
// Launch
// ============================================================
extern "C" void kernel_launch(void* const* d_in, const int* in_sizes, int n_in,
                              void* d_out, int out_size) {
    const float* x    = (const float*)d_in[0];
    const float* W_ih = (const float*)d_in[1];
    const float* W_hh = (const float*)d_in[2];
    const float* b_ih = (const float*)d_in[3];
    const float* b_hh = (const float*)d_in[4];
    const float* W_fc = (const float*)d_in[5];
    const float* b_fc = (const float*)d_in[6];
    float* out = (float*)d_out;

    cudaFuncSetAttribute(gemm_mma, cudaFuncAttributeMaxDynamicSharedMemorySize,
                         MMA_SMEM);
    cudaFuncSetAttribute(lstm_mma, cudaFuncAttributeMaxDynamicSharedMemorySize,
                         L_SMEM);

    prep<<<32, 256>>>(W_ih, b_ih, b_hh);
    prep2<<<8, 256>>>(W_hh);
    gemm_mma<<<BT / 128, 512, MMA_SMEM>>>(x);
    lstm_mma<<<BSZ / LB, 256, L_SMEM>>>(W_fc, b_fc, out);
}

// round 13
// speedup vs baseline: 1.8137x; 1.8137x over previous
#include <cuda_runtime.h>
#include <cuda_bf16.h>
#include <cstdint>

#define BSZ  512
#define TLEN 512
#define IDIM 128
#define HDIM 50
#define ODIM 10
#define GDIM 200              // 4*H
#define BT   (BSZ * TLEN)     // 262144 rows

typedef unsigned long long u64;
typedef unsigned int u32;

// ---- scratch (device globals; no allocation allowed) ----
__device__ u32   g_Bimg[102400 / 4];   // W_ih bf16 hi/lo, mma-fragment-ordered
__device__ float g_bias[GDIM];         // b_ih + b_hh
__device__ float g_xp[BT * GDIM];      // x_proj: [row][g]

// ---- packed f32x2 helpers ----
__device__ __forceinline__ u64 pk2(float lo, float hi) {
    u64 d;
    asm("mov.b64 %0, {%1, %2};" : "=l"(d) : "f"(lo), "f"(hi));
    return d;
}
__device__ __forceinline__ void up2(u64 v, float& lo, float& hi) {
    asm("mov.b64 {%0, %1}, %2;" : "=f"(lo), "=f"(hi) : "l"(v));
}
__device__ __forceinline__ u64 ffma2(u64 a, u64 b, u64 c) {
    u64 d;
    asm("fma.rn.f32x2 %0, %1, %2, %3;" : "=l"(d) : "l"(a), "l"(b), "l"(c));
    return d;
}
__device__ __forceinline__ u64 fadd2(u64 a, u64 b) {
    u64 d;
    asm("add.rn.f32x2 %0, %1, %2;" : "=l"(d) : "l"(a), "l"(b));
    return d;
}
// MUFU.TANH based activations
__device__ __forceinline__ float tanha(float x) {
    float r;
    asm("tanh.approx.f32 %0, %1;" : "=f"(r) : "f"(x));
    return r;
}
__device__ __forceinline__ float sigt(float x) {       // sigmoid via tanh
    return fmaf(0.5f, tanha(0.5f * x), 0.5f);
}
__device__ __forceinline__ void cp16(void* smem, const void* gmem) {
    unsigned sa = (unsigned)__cvta_generic_to_shared(smem);
    asm volatile("cp.async.cg.shared.global [%0], [%1], 16;\n" :: "r"(sa), "l"(gmem));
}
__device__ __forceinline__ void split_bf16(float v, unsigned short& h, unsigned short& l) {
    __nv_bfloat16 hb = __float2bfloat16_rn(v);
    float lf = v - __bfloat162float(hb);
    __nv_bfloat16 lb = __float2bfloat16_rn(lf);
    h = __bfloat16_as_ushort(hb);
    l = __bfloat16_as_ushort(lb);
}
__device__ __forceinline__ void split2(float2 v, u32& hp, u32& lp) {
    unsigned short h0, l0, h1, l1;
    split_bf16(v.x, h0, l0);
    split_bf16(v.y, h1, l1);
    hp = (u32)h0 | ((u32)h1 << 16);
    lp = (u32)l0 | ((u32)l1 << 16);
}
__device__ __forceinline__ void mma16816(float* c, const u32* a, u32 b0, u32 b1) {
    asm volatile(
        "mma.sync.aligned.m16n8k16.row.col.f32.bf16.bf16.f32 "
        "{%0,%1,%2,%3}, {%4,%5,%6,%7}, {%8,%9}, {%0,%1,%2,%3};"
        : "+f"(c[0]), "+f"(c[1]), "+f"(c[2]), "+f"(c[3])
        : "r"(a[0]), "r"(a[1]), "r"(a[2]), "r"(a[3]), "r"(b0), "r"(b1));
}

// ============================================================
// Kernel 0: W_ih fragment image + bias.
// ============================================================
__global__ void prep(const float* __restrict__ W_ih,
                     const float* __restrict__ b_ih,
                     const float* __restrict__ b_hh) {
    int t = threadIdx.x + blockIdx.x * 256;
    for (int idx = t; idx < GDIM * (IDIM / 2); idx += 256 * 32) {
        int g  = idx >> 6;
        int k2 = (idx & 63) * 2;
        u32 hp, lp;
        split2(*(const float2*)&W_ih[g * IDIM + k2], hp, lp);
        int nt = g >> 3, nloc = g & 7;
        int kc = k2 >> 4, kloc = k2 & 15;
        int lane = nloc * 4 + ((kloc & 7) >> 1);
        int reg  = kloc >> 3;
        int base = ((kc * 25 + nt) * 32 + lane) * 4;
        g_Bimg[base + reg]     = hp;
        g_Bimg[base + 2 + reg] = lp;
    }
    if (blockIdx.x == 0 && t < GDIM) g_bias[t] = b_ih[t] + b_hh[t];
}

// ============================================================
// Kernel 1: HMMA GEMM, n-split for 2 blocks/SM.
// Block = (row-tile, n-half). n-half 0: tiles 0..12, half 1: 13..24.
// B slice cp.async -> SMEM (53/49 KB); A frags direct LDG.
// 512 thr / 16 warps: warp w -> m-tile (w&7), n-subrange (w>>3).
// ============================================================
#define SM_BIAS_OFF (13 * 8 * 512)     // max B slice bytes = 53248
#define MMA_SMEM (SM_BIAS_OFF + 800)

__global__ __launch_bounds__(512, 2) void gemm_mma(const float* __restrict__ x) {
    extern __shared__ char sm[];
    u32*   bImg = (u32*)sm;
    float* bias = (float*)(sm + SM_BIAS_OFF);

    const int tid = threadIdx.x;
    const int w   = tid >> 5;
    const int l   = tid & 31;
    const int row0 = (blockIdx.x >> 1) * 128;
    const int nh   = blockIdx.x & 1;          // n-half
    const int n0   = nh * 13;                 // first global n-tile
    const int cnt  = nh ? 12 : 13;            // tiles in this block

    // B slice: cnt tiles per kc, 8 kc. smem [(kc*cnt + ntl)*32 + lane]
    for (int idx = tid; idx < cnt * 256; idx += 512) {
        int kc  = idx / (cnt * 32);
        int rem = idx - kc * (cnt * 32);
        int src = ((kc * 25 + n0) * 32 + rem) * 4;
        cp16(bImg + idx * 4, g_Bimg + src);
    }
    asm volatile("cp.async.commit_group;\n" ::: "memory");
    if (tid < GDIM) bias[tid] = g_bias[tid];

    // warp assignment within the n-half
    const int mt   = w & 7;
    const int nsub = w >> 3;
    const int nst  = nh ? nsub * 6 : nsub * 7;          // local start
    const int cw   = nh ? 6 : (nsub ? 6 : 7);           // tiles this warp

    // per-lane A addrs (m16n8k16 A row-major lane map)
    const int rA = row0 + mt * 16 + (l >> 2);
    const float* xr0 = x + (size_t)rA * IDIM + (l & 3) * 2;
    const float* xr1 = xr0 + 8 * IDIM;

    float acc[7][4];
#pragma unroll
    for (int n = 0; n < 7; n++)
#pragma unroll
        for (int j = 0; j < 4; j++) acc[n][j] = 0.f;

    float2 v0 = *(const float2*)(xr0);
    float2 v1 = *(const float2*)(xr1);
    float2 v2 = *(const float2*)(xr0 + 8);
    float2 v3 = *(const float2*)(xr1 + 8);

    asm volatile("cp.async.wait_group 0;\n" ::: "memory");
    __syncthreads();

#pragma unroll
    for (int kc = 0; kc < 8; kc++) {
        u32 ahr[4], alr[4];
        split2(v0, ahr[0], alr[0]);
        split2(v1, ahr[1], alr[1]);
        split2(v2, ahr[2], alr[2]);
        split2(v3, ahr[3], alr[3]);
        if (kc + 1 < 8) {
            int ko = (kc + 1) * 16;
            v0 = *(const float2*)(xr0 + ko);
            v1 = *(const float2*)(xr1 + ko);
            v2 = *(const float2*)(xr0 + ko + 8);
            v3 = *(const float2*)(xr1 + ko + 8);
        }
#pragma unroll
        for (int n = 0; n < 7; n++) {
            if (n < cw) {
                uint4 b = *(const uint4*)&bImg[((kc * cnt + nst + n) * 32 + l) * 4];
                mma16816(acc[n], ahr, b.x, b.y);   // hi*hi
                mma16816(acc[n], ahr, b.z, b.w);   // hi*lo
                mma16816(acc[n], alr, b.x, b.y);   // lo*hi
            }
        }
    }

    // epilogue
    {
        int r0 = row0 + mt * 16 + (l >> 2);
        int r1 = r0 + 8;
#pragma unroll
        for (int n = 0; n < 7; n++) {
            if (n < cw) {
                int c = (n0 + nst + n) * 8 + (l & 3) * 2;
                float2 bv = *(const float2*)&bias[c];
                float2 o0 = make_float2(acc[n][0] + bv.x, acc[n][1] + bv.y);
                float2 o1 = make_float2(acc[n][2] + bv.x, acc[n][3] + bv.y);
                *(float2*)&g_xp[(size_t)r0 * GDIM + c] = o0;
                *(float2*)&g_xp[(size_t)r1 * GDIM + c] = o1;
            }
        }
    }
}

// ============================================================
// Kernel 2: LSTM recurrence + FC head (R3 structure, measured
// 361us) with MUFU.TANH activations.
// 2 batches/block, grid 256, W_hh dup-pairs in registers.
// ============================================================
__global__ __launch_bounds__(224, 2) void lstm_rec(
    const float* __restrict__ W_hh, const float* __restrict__ W_fc,
    const float* __restrict__ b_fc, float* __restrict__ out)
{
    __shared__ alignas(16) float2 h_sh[HDIM];
    __shared__ alignas(16) float2 gate_sh[GDIM];
    const int b0 = blockIdx.x * 2;
    const int g = threadIdx.x;

    u64 w2[HDIM];
    if (g < GDIM) {
#pragma unroll
        for (int j = 0; j < HDIM; j++) {
            float w = W_hh[g * HDIM + j];
            w2[j] = pk2(w, w);
        }
    }
    if (g < HDIM) h_sh[g] = make_float2(0.f, 0.f);
    float c0 = 0.f, c1 = 0.f;

    const float* xp0 = g_xp + (size_t)b0 * (TLEN * GDIM);
    const float* xp1 = xp0 + (size_t)(TLEN * GDIM);
    float xc0 = 0.f, xc1 = 0.f;
    if (g < GDIM) { xc0 = xp0[g]; xc1 = xp1[g]; }
    const bool isg = (g >= 2 * HDIM && g < 3 * HDIM);   // tanh gate
    __syncthreads();

    for (int t = 0; t < TLEN; t++) {
        if (g < GDIM) {
            u64 accA = pk2(xc0, xc1);
            u64 accB = 0ull;
            if (t + 1 < TLEN) {                          // prefetch next step
                xc0 = xp0[(t + 1) * GDIM + g];
                xc1 = xp1[(t + 1) * GDIM + g];
            }
#pragma unroll
            for (int j = 0; j < HDIM; j += 2) {
                ulonglong2 hv = *(const ulonglong2*)(h_sh + j);
                accA = ffma2(hv.x, w2[j],     accA);
                accB = ffma2(hv.y, w2[j + 1], accB);
            }
            float a0, a1;
            up2(fadd2(accA, accB), a0, a1);
            float r0 = isg ? tanha(a0) : sigt(a0);
            float r1 = isg ? tanha(a1) : sigt(a1);
            gate_sh[g] = make_float2(r0, r1);
        }
        __syncthreads();
        if (g < HDIM) {
            float2 iv = gate_sh[g];
            float2 fv = gate_sh[g + HDIM];
            float2 gv = gate_sh[g + 2 * HDIM];
            float2 ov = gate_sh[g + 3 * HDIM];
            c0 = fmaf(fv.x, c0, iv.x * gv.x);
            c1 = fmaf(fv.y, c1, iv.y * gv.y);
            h_sh[g] = make_float2(ov.x * tanha(c0), ov.y * tanha(c1));
        }
        __syncthreads();
    }

    // FC head for both batches
    if (g < ODIM) {
        float a0 = b_fc[g], a1 = a0;
#pragma unroll
        for (int j = 0; j < HDIM; j++) {
            float2 h = h_sh[j];
            float w = W_fc[g * HDIM + j];
            a0 = fmaf(h.x, w, a0);
            a1 = fmaf(h.y, w, a1);
        }
        out[b0 * ODIM + g]       = a0;
        out[(b0 + 1) * ODIM + g] = a1;
    }
}

// ============================================================
// Launch
// ============================================================
extern "C" void kernel_launch(void* const* d_in, const int* in_sizes, int n_in,
                              void* d_out, int out_size) {
    const float* x    = (const float*)d_in[0];
    const float* W_ih = (const float*)d_in[1];
    const float* W_hh = (const float*)d_in[2];
    const float* b_ih = (const float*)d_in[3];
    const float* b_hh = (const float*)d_in[4];
    const float* W_fc = (const float*)d_in[5];
    const float* b_fc = (const float*)d_in[6];
    float* out = (float*)d_out;

    cudaFuncSetAttribute(gemm_mma, cudaFuncAttributeMaxDynamicSharedMemorySize,
                         MMA_SMEM);

    prep<<<32, 256>>>(W_ih, b_ih, b_hh);
    gemm_mma<<<(BT / 128) * 2, 512, MMA_SMEM>>>(x);
    lstm_rec<<<BSZ / 2, 224>>>(W_hh, W_fc, b_fc, out);
}

// round 14
// speedup vs baseline: 2.0006x; 1.1031x over previous
#include <cuda_runtime.h>
#include <cuda_bf16.h>
#include <cstdint>

#define BSZ  512
#define TLEN 512
#define IDIM 128
#define HDIM 50
#define ODIM 10
#define GDIM 200              // 4*H
#define BT   (BSZ * TLEN)     // 262144 rows

typedef unsigned long long u64;
typedef unsigned int u32;

// ---- scratch (device globals; no allocation allowed) ----
__device__ u32   g_Bimg[102400 / 4];   // W_ih bf16 hi/lo, mma-fragment-ordered
__device__ float g_bias[GDIM];         // b_ih + b_hh
__device__ float g_xp[BT * GDIM];      // x_proj: [row][g]

// ---- packed f32x2 helpers ----
__device__ __forceinline__ u64 pk2(float lo, float hi) {
    u64 d;
    asm("mov.b64 %0, {%1, %2};" : "=l"(d) : "f"(lo), "f"(hi));
    return d;
}
__device__ __forceinline__ void up2(u64 v, float& lo, float& hi) {
    asm("mov.b64 {%0, %1}, %2;" : "=f"(lo), "=f"(hi) : "l"(v));
}
__device__ __forceinline__ u64 ffma2(u64 a, u64 b, u64 c) {
    u64 d;
    asm("fma.rn.f32x2 %0, %1, %2, %3;" : "=l"(d) : "l"(a), "l"(b), "l"(c));
    return d;
}
__device__ __forceinline__ u64 fadd2(u64 a, u64 b) {
    u64 d;
    asm("add.rn.f32x2 %0, %1, %2;" : "=l"(d) : "l"(a), "l"(b));
    return d;
}
// MUFU.TANH based activations
__device__ __forceinline__ float tanha(float x) {
    float r;
    asm("tanh.approx.f32 %0, %1;" : "=f"(r) : "f"(x));
    return r;
}
__device__ __forceinline__ float sigt(float x) {       // sigmoid via tanh
    return fmaf(0.5f, tanha(0.5f * x), 0.5f);
}
__device__ __forceinline__ void cp16(void* smem, const void* gmem) {
    unsigned sa = (unsigned)__cvta_generic_to_shared(smem);
    asm volatile("cp.async.cg.shared.global [%0], [%1], 16;\n" :: "r"(sa), "l"(gmem));
}
__device__ __forceinline__ void split_bf16(float v, unsigned short& h, unsigned short& l) {
    __nv_bfloat16 hb = __float2bfloat16_rn(v);
    float lf = v - __bfloat162float(hb);
    __nv_bfloat16 lb = __float2bfloat16_rn(lf);
    h = __bfloat16_as_ushort(hb);
    l = __bfloat16_as_ushort(lb);
}
__device__ __forceinline__ void split2(float2 v, u32& hp, u32& lp) {
    unsigned short h0, l0, h1, l1;
    split_bf16(v.x, h0, l0);
    split_bf16(v.y, h1, l1);
    hp = (u32)h0 | ((u32)h1 << 16);
    lp = (u32)l0 | ((u32)l1 << 16);
}
__device__ __forceinline__ void mma16816(float* c, const u32* a, u32 b0, u32 b1) {
    asm volatile(
        "mma.sync.aligned.m16n8k16.row.col.f32.bf16.bf16.f32 "
        "{%0,%1,%2,%3}, {%4,%5,%6,%7}, {%8,%9}, {%0,%1,%2,%3};"
        : "+f"(c[0]), "+f"(c[1]), "+f"(c[2]), "+f"(c[3])
        : "r"(a[0]), "r"(a[1]), "r"(a[2]), "r"(a[3]), "r"(b0), "r"(b1));
}

// ============================================================
// Kernel 0: W_ih fragment image + bias.
// ============================================================
__global__ void prep(const float* __restrict__ W_ih,
                     const float* __restrict__ b_ih,
                     const float* __restrict__ b_hh) {
    int t = threadIdx.x + blockIdx.x * 256;
    for (int idx = t; idx < GDIM * (IDIM / 2); idx += 256 * 32) {
        int g  = idx >> 6;
        int k2 = (idx & 63) * 2;
        u32 hp, lp;
        split2(*(const float2*)&W_ih[g * IDIM + k2], hp, lp);
        int nt = g >> 3, nloc = g & 7;
        int kc = k2 >> 4, kloc = k2 & 15;
        int lane = nloc * 4 + ((kloc & 7) >> 1);
        int reg  = kloc >> 3;
        int base = ((kc * 25 + nt) * 32 + lane) * 4;
        g_Bimg[base + reg]     = hp;
        g_Bimg[base + 2 + reg] = lp;
    }
    if (blockIdx.x == 0 && t < GDIM) g_bias[t] = b_ih[t] + b_hh[t];
}

// ============================================================
// Kernel 1: HMMA GEMM, n-split, 2 blocks/SM (R13, measured).
// ============================================================
#define SM_BIAS_OFF (13 * 8 * 512)     // max B slice bytes = 53248
#define MMA_SMEM (SM_BIAS_OFF + 800)

__global__ __launch_bounds__(512, 2) void gemm_mma(const float* __restrict__ x) {
    extern __shared__ char sm[];
    u32*   bImg = (u32*)sm;
    float* bias = (float*)(sm + SM_BIAS_OFF);

    const int tid = threadIdx.x;
    const int w   = tid >> 5;
    const int l   = tid & 31;
    const int row0 = (blockIdx.x >> 1) * 128;
    const int nh   = blockIdx.x & 1;
    const int n0   = nh * 13;
    const int cnt  = nh ? 12 : 13;

    for (int idx = tid; idx < cnt * 256; idx += 512) {
        int kc  = idx / (cnt * 32);
        int rem = idx - kc * (cnt * 32);
        int src = ((kc * 25 + n0) * 32 + rem) * 4;
        cp16(bImg + idx * 4, g_Bimg + src);
    }
    asm volatile("cp.async.commit_group;\n" ::: "memory");
    if (tid < GDIM) bias[tid] = g_bias[tid];

    const int mt   = w & 7;
    const int nsub = w >> 3;
    const int nst  = nh ? nsub * 6 : nsub * 7;
    const int cw   = nh ? 6 : (nsub ? 6 : 7);

    const int rA = row0 + mt * 16 + (l >> 2);
    const float* xr0 = x + (size_t)rA * IDIM + (l & 3) * 2;
    const float* xr1 = xr0 + 8 * IDIM;

    float acc[7][4];
#pragma unroll
    for (int n = 0; n < 7; n++)
#pragma unroll
        for (int j = 0; j < 4; j++) acc[n][j] = 0.f;

    float2 v0 = *(const float2*)(xr0);
    float2 v1 = *(const float2*)(xr1);
    float2 v2 = *(const float2*)(xr0 + 8);
    float2 v3 = *(const float2*)(xr1 + 8);

    asm volatile("cp.async.wait_group 0;\n" ::: "memory");
    __syncthreads();

#pragma unroll
    for (int kc = 0; kc < 8; kc++) {
        u32 ahr[4], alr[4];
        split2(v0, ahr[0], alr[0]);
        split2(v1, ahr[1], alr[1]);
        split2(v2, ahr[2], alr[2]);
        split2(v3, ahr[3], alr[3]);
        if (kc + 1 < 8) {
            int ko = (kc + 1) * 16;
            v0 = *(const float2*)(xr0 + ko);
            v1 = *(const float2*)(xr1 + ko);
            v2 = *(const float2*)(xr0 + ko + 8);
            v3 = *(const float2*)(xr1 + ko + 8);
        }
#pragma unroll
        for (int n = 0; n < 7; n++) {
            if (n < cw) {
                uint4 b = *(const uint4*)&bImg[((kc * cnt + nst + n) * 32 + l) * 4];
                mma16816(acc[n], ahr, b.x, b.y);
                mma16816(acc[n], ahr, b.z, b.w);
                mma16816(acc[n], alr, b.x, b.y);
            }
        }
    }
    {
        int r0 = row0 + mt * 16 + (l >> 2);
        int r1 = r0 + 8;
#pragma unroll
        for (int n = 0; n < 7; n++) {
            if (n < cw) {
                int c = (n0 + nst + n) * 8 + (l & 3) * 2;
                float2 bv = *(const float2*)&bias[c];
                float2 o0 = make_float2(acc[n][0] + bv.x, acc[n][1] + bv.y);
                float2 o1 = make_float2(acc[n][2] + bv.x, acc[n][3] + bv.y);
                *(float2*)&g_xp[(size_t)r0 * GDIM + c] = o0;
                *(float2*)&g_xp[(size_t)r1 * GDIM + c] = o1;
            }
        }
    }
}

// ============================================================
// Kernel 2: LSTM recurrence + FC head, 1 batch/block, grid 512,
// 4 blocks/SM. f32x2 packed along K: acc += {h_j,h_j+1}*{w_j,w_j+1}.
// Weights = 25 natural float2 pairs in regs (50 regs, no dup).
// ============================================================
__global__ __launch_bounds__(224, 4) void lstm_rec(
    const float* __restrict__ W_hh, const float* __restrict__ W_fc,
    const float* __restrict__ b_fc, float* __restrict__ out)
{
    __shared__ alignas(16) float h_sh[52];      // 50 + pad
    __shared__ alignas(16) float gate_sh[GDIM];
    const int b = blockIdx.x;
    const int g = threadIdx.x;

    u64 w2[25];                                 // {w[2j], w[2j+1]} pairs
    if (g < GDIM) {
#pragma unroll
        for (int j = 0; j < 25; j++) {
            float2 wv = *(const float2*)&W_hh[g * HDIM + 2 * j];
            w2[j] = pk2(wv.x, wv.y);
        }
    }
    if (g < HDIM) h_sh[g] = 0.f;
    float c = 0.f;

    const float* xp = g_xp + (size_t)b * (TLEN * GDIM);
    float xc = (g < GDIM) ? xp[g] : 0.f;
    const bool isg = (g >= 2 * HDIM && g < 3 * HDIM);   // tanh gate
    __syncthreads();

    for (int t = 0; t < TLEN; t++) {
        if (g < GDIM) {
            u64 accA = pk2(xc, 0.f);
            u64 accB = 0ull;
            if (t + 1 < TLEN) xc = xp[(t + 1) * GDIM + g];   // prefetch
#pragma unroll
            for (int j = 0; j < 48; j += 4) {
                ulonglong2 hv = *(const ulonglong2*)&h_sh[j]; // {h[j],h[j+1]},{h[j+2],h[j+3]}
                accA = ffma2(hv.x, w2[j >> 1],       accA);
                accB = ffma2(hv.y, w2[(j >> 1) + 1], accB);
            }
            {
                u64 hv = *(const u64*)&h_sh[48];
                accA = ffma2(hv, w2[24], accA);
            }
            float a0, a1;
            up2(fadd2(accA, accB), a0, a1);
            float a = a0 + a1;
            gate_sh[g] = isg ? tanha(a) : sigt(a);
        }
        __syncthreads();
        if (g < HDIM) {
            float iv = gate_sh[g];
            float fv = gate_sh[g + HDIM];
            float gv = gate_sh[g + 2 * HDIM];
            float ov = gate_sh[g + 3 * HDIM];
            c = fmaf(fv, c, iv * gv);
            h_sh[g] = ov * tanha(c);
        }
        __syncthreads();
    }

    // FC head
    if (g < ODIM) {
        float a = b_fc[g];
#pragma unroll
        for (int j = 0; j < HDIM; j++)
            a = fmaf(h_sh[j], W_fc[g * HDIM + j], a);
        out[b * ODIM + g] = a;
    }
}

// ============================================================
// Launch
// ============================================================
extern "C" void kernel_launch(void* const* d_in, const int* in_sizes, int n_in,
                              void* d_out, int out_size) {
    const float* x    = (const float*)d_in[0];
    const float* W_ih = (const float*)d_in[1];
    const float* W_hh = (const float*)d_in[2];
    const float* b_ih = (const float*)d_in[3];
    const float* b_hh = (const float*)d_in[4];
    const float* W_fc = (const float*)d_in[5];
    const float* b_fc = (const float*)d_in[6];
    float* out = (float*)d_out;

    cudaFuncSetAttribute(gemm_mma, cudaFuncAttributeMaxDynamicSharedMemorySize,
                         MMA_SMEM);

    prep<<<32, 256>>>(W_ih, b_ih, b_hh);
    gemm_mma<<<(BT / 128) * 2, 512, MMA_SMEM>>>(x);
    lstm_rec<<<BSZ, 224>>>(W_hh, W_fc, b_fc, out);
}

// round 15
// speedup vs baseline: 2.0510x; 1.0252x over previous
#include <cuda_runtime.h>
#include <cuda_bf16.h>
#include <cuda_fp16.h>
#include <cstdint>

#define BSZ  512
#define TLEN 512
#define IDIM 128
#define HDIM 50
#define ODIM 10
#define GDIM 200              // 4*H
#define BT   (BSZ * TLEN)     // 262144 rows

typedef unsigned long long u64;
typedef unsigned int u32;

// ---- scratch (device globals; no allocation allowed) ----
__device__ u32   g_Bimg[102400 / 4];        // W_ih bf16 hi/lo frag image (prescaled i/f/o)
__device__ float g_Whs[GDIM * HDIM];        // W_hh prescaled copy
__device__ float g_bias[GDIM];              // (b_ih + b_hh) prescaled
__device__ unsigned short g_xph[(size_t)BT * GDIM];   // x_proj in fp16

// ---- packed f32x2 helpers ----
__device__ __forceinline__ u64 pk2(float lo, float hi) {
    u64 d;
    asm("mov.b64 %0, {%1, %2};" : "=l"(d) : "f"(lo), "f"(hi));
    return d;
}
__device__ __forceinline__ void up2(u64 v, float& lo, float& hi) {
    asm("mov.b64 {%0, %1}, %2;" : "=f"(lo), "=f"(hi) : "l"(v));
}
__device__ __forceinline__ u64 ffma2(u64 a, u64 b, u64 c) {
    u64 d;
    asm("fma.rn.f32x2 %0, %1, %2, %3;" : "=l"(d) : "l"(a), "l"(b), "l"(c));
    return d;
}
__device__ __forceinline__ u64 fadd2(u64 a, u64 b) {
    u64 d;
    asm("add.rn.f32x2 %0, %1, %2;" : "=l"(d) : "l"(a), "l"(b));
    return d;
}
__device__ __forceinline__ float tanha(float x) {
    float r;
    asm("tanh.approx.f32 %0, %1;" : "=f"(r) : "f"(x));
    return r;
}
__device__ __forceinline__ void cp16(void* smem, const void* gmem) {
    unsigned sa = (unsigned)__cvta_generic_to_shared(smem);
    asm volatile("cp.async.cg.shared.global [%0], [%1], 16;\n" :: "r"(sa), "l"(gmem));
}
// slow exact split (prep only)
__device__ __forceinline__ void split_bf16(float v, unsigned short& h, unsigned short& l) {
    __nv_bfloat16 hb = __float2bfloat16_rn(v);
    float lf = v - __bfloat162float(hb);
    __nv_bfloat16 lb = __float2bfloat16_rn(lf);
    h = __bfloat16_as_ushort(hb);
    l = __bfloat16_as_ushort(lb);
}
__device__ __forceinline__ void split2(float2 v, u32& hp, u32& lp) {
    unsigned short h0, l0, h1, l1;
    split_bf16(v.x, h0, l0);
    split_bf16(v.y, h1, l1);
    hp = (u32)h0 | ((u32)h1 << 16);
    lp = (u32)l0 | ((u32)l1 << 16);
}
// fast split: 1 packed cvt for hi, shift/mask reconstruct, 2 subs, 1 packed cvt for lo
__device__ __forceinline__ void split2f(float2 v, u32& hp, u32& lp) {
    asm("cvt.rn.satfinite.bf16x2.f32 %0, %1, %2;" : "=r"(hp) : "f"(v.y), "f"(v.x));
    float h0 = __uint_as_float(hp << 16);
    float h1 = __uint_as_float(hp & 0xffff0000u);
    float l0 = v.x - h0;
    float l1 = v.y - h1;
    asm("cvt.rn.satfinite.bf16x2.f32 %0, %1, %2;" : "=r"(lp) : "f"(l1), "f"(l0));
}
__device__ __forceinline__ void mma16816(float* c, const u32* a, u32 b0, u32 b1) {
    asm volatile(
        "mma.sync.aligned.m16n8k16.row.col.f32.bf16.bf16.f32 "
        "{%0,%1,%2,%3}, {%4,%5,%6,%7}, {%8,%9}, {%0,%1,%2,%3};"
        : "+f"(c[0]), "+f"(c[1]), "+f"(c[2]), "+f"(c[3])
        : "r"(a[0]), "r"(a[1]), "r"(a[2]), "r"(a[3]), "r"(b0), "r"(b1));
}

// ============================================================
// Kernel 0: W_ih fragment image + bias, i/f/o rows prescaled 0.5.
// ============================================================
__global__ void prep(const float* __restrict__ W_ih,
                     const float* __restrict__ b_ih,
                     const float* __restrict__ b_hh) {
    int t = threadIdx.x + blockIdx.x * 256;
    for (int idx = t; idx < GDIM * (IDIM / 2); idx += 256 * 32) {
        int g  = idx >> 6;
        int k2 = (idx & 63) * 2;
        float s = (g < 100 || g >= 150) ? 0.5f : 1.0f;
        float2 wv = *(const float2*)&W_ih[g * IDIM + k2];
        wv.x *= s; wv.y *= s;
        u32 hp, lp;
        split2(wv, hp, lp);
        int nt = g >> 3, nloc = g & 7;
        int kc = k2 >> 4, kloc = k2 & 15;
        int lane = nloc * 4 + ((kloc & 7) >> 1);
        int reg  = kloc >> 3;
        int base = ((kc * 25 + nt) * 32 + lane) * 4;
        g_Bimg[base + reg]     = hp;
        g_Bimg[base + 2 + reg] = lp;
    }
    if (blockIdx.x == 0 && t < GDIM) {
        float s = (t < 100 || t >= 150) ? 0.5f : 1.0f;
        g_bias[t] = (b_ih[t] + b_hh[t]) * s;
    }
}

// ============================================================
// Kernel 0b: prescaled W_hh copy.
// ============================================================
__global__ void prep2(const float* __restrict__ W_hh) {
    int t = threadIdx.x + blockIdx.x * 256;
    if (t < GDIM * HDIM) {
        int g = t / HDIM;
        float s = (g < 100 || g >= 150) ? 0.5f : 1.0f;
        g_Whs[t] = W_hh[t] * s;
    }
}

// ============================================================
// Kernel 1: HMMA GEMM, n-split, 2 blocks/SM; fp16 output.
// ============================================================
#define SM_BIAS_OFF (13 * 8 * 512)     // max B slice bytes = 53248
#define MMA_SMEM (SM_BIAS_OFF + 800)

__global__ __launch_bounds__(512, 2) void gemm_mma(const float* __restrict__ x) {
    extern __shared__ char sm[];
    u32*   bImg = (u32*)sm;
    float* bias = (float*)(sm + SM_BIAS_OFF);

    const int tid = threadIdx.x;
    const int w   = tid >> 5;
    const int l   = tid & 31;
    const int row0 = (blockIdx.x >> 1) * 128;
    const int nh   = blockIdx.x & 1;
    const int n0   = nh * 13;
    const int cnt  = nh ? 12 : 13;

    for (int idx = tid; idx < cnt * 256; idx += 512) {
        int kc  = idx / (cnt * 32);
        int rem = idx - kc * (cnt * 32);
        int src = ((kc * 25 + n0) * 32 + rem) * 4;
        cp16(bImg + idx * 4, g_Bimg + src);
    }
    asm volatile("cp.async.commit_group;\n" ::: "memory");
    if (tid < GDIM) bias[tid] = g_bias[tid];

    const int mt   = w & 7;
    const int nsub = w >> 3;
    const int nst  = nh ? nsub * 6 : nsub * 7;
    const int cw   = nh ? 6 : (nsub ? 6 : 7);

    const int rA = row0 + mt * 16 + (l >> 2);
    const float* xr0 = x + (size_t)rA * IDIM + (l & 3) * 2;
    const float* xr1 = xr0 + 8 * IDIM;

    float acc[7][4];
#pragma unroll
    for (int n = 0; n < 7; n++)
#pragma unroll
        for (int j = 0; j < 4; j++) acc[n][j] = 0.f;

    float2 v0 = *(const float2*)(xr0);
    float2 v1 = *(const float2*)(xr1);
    float2 v2 = *(const float2*)(xr0 + 8);
    float2 v3 = *(const float2*)(xr1 + 8);

    asm volatile("cp.async.wait_group 0;\n" ::: "memory");
    __syncthreads();

#pragma unroll
    for (int kc = 0; kc < 8; kc++) {
        u32 ahr[4], alr[4];
        split2f(v0, ahr[0], alr[0]);
        split2f(v1, ahr[1], alr[1]);
        split2f(v2, ahr[2], alr[2]);
        split2f(v3, ahr[3], alr[3]);
        if (kc + 1 < 8) {
            int ko = (kc + 1) * 16;
            v0 = *(const float2*)(xr0 + ko);
            v1 = *(const float2*)(xr1 + ko);
            v2 = *(const float2*)(xr0 + ko + 8);
            v3 = *(const float2*)(xr1 + ko + 8);
        }
#pragma unroll
        for (int n = 0; n < 7; n++) {
            if (n < cw) {
                uint4 b = *(const uint4*)&bImg[((kc * cnt + nst + n) * 32 + l) * 4];
                mma16816(acc[n], ahr, b.x, b.y);
                mma16816(acc[n], ahr, b.z, b.w);
                mma16816(acc[n], alr, b.x, b.y);
            }
        }
    }

    // epilogue: add bias, pack fp16x2, store
    {
        int r0 = row0 + mt * 16 + (l >> 2);
        int r1 = r0 + 8;
#pragma unroll
        for (int n = 0; n < 7; n++) {
            if (n < cw) {
                int c = (n0 + nst + n) * 8 + (l & 3) * 2;
                float2 bv = *(const float2*)&bias[c];
                float o00 = acc[n][0] + bv.x, o01 = acc[n][1] + bv.y;
                float o10 = acc[n][2] + bv.x, o11 = acc[n][3] + bv.y;
                u32 p0, p1;
                asm("cvt.rn.f16x2.f32 %0, %1, %2;" : "=r"(p0) : "f"(o01), "f"(o00));
                asm("cvt.rn.f16x2.f32 %0, %1, %2;" : "=r"(p1) : "f"(o11), "f"(o10));
                *(u32*)&g_xph[(size_t)r0 * GDIM + c] = p0;
                *(u32*)&g_xph[(size_t)r1 * GDIM + c] = p1;
            }
        }
    }
}

// ============================================================
// Kernel 2: LSTM recurrence + FC head, 1 batch/block, grid 512,
// 4 blocks/SM, K-packed f32x2, prescaled activations, fp16 x_proj.
// ============================================================
__global__ __launch_bounds__(224, 4) void lstm_rec(
    const float* __restrict__ W_fc, const float* __restrict__ b_fc,
    float* __restrict__ out)
{
    __shared__ alignas(16) float h_sh[52];      // 50 + pad
    __shared__ alignas(16) float gate_sh[GDIM];
    const int b = blockIdx.x;
    const int g = threadIdx.x;

    u64 w2[25];                                 // {w[2j], w[2j+1]} pairs (prescaled)
    if (g < GDIM) {
#pragma unroll
        for (int j = 0; j < 25; j++) {
            float2 wv = *(const float2*)&g_Whs[g * HDIM + 2 * j];
            w2[j] = pk2(wv.x, wv.y);
        }
    }
    if (g < HDIM) h_sh[g] = 0.f;
    float c = 0.f;

    const unsigned short* xp = g_xph + (size_t)b * (TLEN * GDIM);
    unsigned short xc = 0;
    if (g < GDIM) xc = xp[g];
    const bool isg = (g >= 2 * HDIM && g < 3 * HDIM);   // tanh gate
    __syncthreads();

    for (int t = 0; t < TLEN; t++) {
        if (g < GDIM) {
            float xcf;
            asm("cvt.f32.f16 %0, %1;" : "=f"(xcf) : "h"(xc));
            u64 accA = pk2(xcf, 0.f);
            u64 accB = 0ull;
            if (t + 1 < TLEN) xc = xp[(t + 1) * GDIM + g];   // prefetch
#pragma unroll
            for (int j = 0; j < 48; j += 4) {
                ulonglong2 hv = *(const ulonglong2*)&h_sh[j];
                accA = ffma2(hv.x, w2[j >> 1],       accA);
                accB = ffma2(hv.y, w2[(j >> 1) + 1], accB);
            }
            {
                u64 hv = *(const u64*)&h_sh[48];
                accA = ffma2(hv, w2[24], accA);
            }
            float a0, a1;
            up2(fadd2(accA, accB), a0, a1);
            float a = a0 + a1;
            // i/f/o rows prescaled by 0.5: sigmoid = 0.5*tanh(0.5x)+0.5
            gate_sh[g] = isg ? tanha(a) : fmaf(0.5f, tanha(a), 0.5f);
        }
        __syncthreads();
        if (g < HDIM) {
            float iv = gate_sh[g];
            float fv = gate_sh[g + HDIM];
            float gv = gate_sh[g + 2 * HDIM];
            float ov = gate_sh[g + 3 * HDIM];
            c = fmaf(fv, c, iv * gv);
            h_sh[g] = ov * tanha(c);
        }
        __syncthreads();
    }

    // FC head
    if (g < ODIM) {
        float a = b_fc[g];
#pragma unroll
        for (int j = 0; j < HDIM; j++)
            a = fmaf(h_sh[j], W_fc[g * HDIM + j], a);
        out[b * ODIM + g] = a;
    }
}

// ============================================================
// Launch
// ============================================================
extern "C" void kernel_launch(void* const* d_in, const int* in_sizes, int n_in,
                              void* d_out, int out_size) {
    const float* x    = (const float*)d_in[0];
    const float* W_ih = (const float*)d_in[1];
    const float* W_hh = (const float*)d_in[2];
    const float* b_ih = (const float*)d_in[3];
    const float* b_hh = (const float*)d_in[4];
    const float* W_fc = (const float*)d_in[5];
    const float* b_fc = (const float*)d_in[6];
    float* out = (float*)d_out;

    cudaFuncSetAttribute(gemm_mma, cudaFuncAttributeMaxDynamicSharedMemorySize,
                         MMA_SMEM);

    prep<<<32, 256>>>(W_ih, b_ih, b_hh);
    prep2<<<40, 256>>>(W_hh);
    gemm_mma<<<(BT / 128) * 2, 512, MMA_SMEM>>>(x);
    lstm_rec<<<BSZ, 224>>>(W_fc, b_fc, out);
}